// round 1
// baseline (speedup 1.0000x reference)
#include <cuda_runtime.h>

// LDR toeplitz-displacement layer via FFT, exactly mirroring the reference:
//   Hf = fft(D*H); Gf = fft(G); Xf = ifft(conj(D)*x)
//   Yf[j,b] = sum_{i,s} Gf[i,j,s] * fft( D * fft( Hf[i,j,s] * Xf[i,b] ) )
//   out[j,b] = Re( ifft( Yf[j,b] ) )
// All FFTs are 4096-pt radix-4 Stockham autosort in shared memory.

#define NN    4096
#define NT    512
#define CIN   4
#define COUT  4
#define RANK  4
#define BATCH 32

// scratch (allocation-free: __device__ globals)
__device__ float2 g_Hf[CIN*COUT*RANK][NN];   // 2 MB
__device__ float2 g_Gf[CIN*COUT*RANK][NN];   // 2 MB
__device__ float2 g_Xf[CIN*BATCH][NN];       // 4 MB

__device__ __forceinline__ float2 cmul(float2 a, float2 b) {
    return make_float2(a.x*b.x - a.y*b.y, a.x*b.y + a.y*b.x);
}
__device__ __forceinline__ float2 cadd(float2 a, float2 b) { return make_float2(a.x+b.x, a.y+b.y); }
__device__ __forceinline__ float2 csub(float2 a, float2 b) { return make_float2(a.x-b.x, a.y-b.y); }

// Fill forward twiddle table W[k] = exp(-2*pi*i*k/4096), k in [0, 3072)
__device__ __forceinline__ void fill_twiddles(float2* W, int tid) {
    for (int k = tid; k < 3072; k += NT) {
        float s, c;
        sincospif((float)k * (1.0f / 2048.0f), &s, &c);
        W[k] = make_float2(c, -s);
    }
}

// 4096-pt radix-4 Stockham FFT. Input in buf0, output in buf0 (6 stages, even #swaps).
// INV=0: forward (W^-). INV=1: inverse WITHOUT the 1/N scale (caller applies).
template<int INV>
__device__ void fft4096(float2* __restrict__ buf0, float2* __restrict__ buf1,
                        const float2* __restrict__ W, int tid)
{
    float2* src = buf0;
    float2* dst = buf1;
#pragma unroll
    for (int stage = 0; stage < 6; ++stage) {
        const int s = 1 << (2 * stage);
        __syncthreads();   // writes of previous stage (or caller fill) -> reads here
#pragma unroll
        for (int it = 0; it < (NN/4) / NT; ++it) {
            int u  = tid + it * NT;          // u in [0, 1024)
            int k1 = u & ~(s - 1);           // = p*s, twiddle base exponent
            float2 a = src[u];
            float2 b = src[u + 1024];
            float2 c = src[u + 2048];
            float2 d = src[u + 3072];
            float2 t0 = cadd(a, c);
            float2 t1 = csub(a, c);
            float2 t2 = cadd(b, d);
            float2 bd = csub(b, d);
            // forward: t3 = -i*(b-d); inverse: t3 = +i*(b-d)
            float2 t3 = INV ? make_float2(-bd.y, bd.x) : make_float2(bd.y, -bd.x);
            float2 o0 = cadd(t0, t2);
            float2 o1 = cadd(t1, t3);
            float2 o2 = csub(t0, t2);
            float2 o3 = csub(t1, t3);
            float2 w1 = W[k1];
            float2 w2 = W[2 * k1];
            float2 w3 = W[3 * k1];
            if (INV) { w1.y = -w1.y; w2.y = -w2.y; w3.y = -w3.y; }
            int base = u + 3 * k1;           // = q + s*(4p)
            dst[base]         = o0;
            dst[base + s]     = cmul(o1, w1);
            dst[base + 2*s]   = cmul(o2, w2);
            dst[base + 3*s]   = cmul(o3, w3);
        }
        float2* tmp = src; src = dst; dst = tmp;
    }
    __syncthreads();  // result (in buf0) visible to all
}

// smem layout prep: buf0[4096] buf1[4096] W[3072]  -> 11264 float2 = 88 KB
#define PREP_SMEM (11264 * (int)sizeof(float2))
// smem layout main: buf0[4096] buf1[4096] acc[4096] W[3072] -> 15360 float2 = 120 KB
#define MAIN_SMEM (15360 * (int)sizeof(float2))

__global__ void __launch_bounds__(NT) ldr_prep_kernel(const float* __restrict__ x,
                                                      const float* __restrict__ G,
                                                      const float* __restrict__ H)
{
    extern __shared__ float2 s_mem[];
    float2* buf0 = s_mem;
    float2* buf1 = s_mem + NN;
    float2* W    = s_mem + 2 * NN;
    const int tid = threadIdx.x;
    fill_twiddles(W, tid);

    const int bid = blockIdx.x;
    if (bid < 64) {
        // Hf[row] = fft(D * H[row]),  D[n] = exp(i*pi*n/N)
        const float* h = H + bid * NN;
        for (int n = tid; n < NN; n += NT) {
            float s, c; sincospif((float)n * (1.0f / 4096.0f), &s, &c);
            float v = h[n];
            buf0[n] = make_float2(v * c, v * s);
        }
        fft4096<0>(buf0, buf1, W, tid);
        for (int n = tid; n < NN; n += NT) g_Hf[bid][n] = buf0[n];
    } else if (bid < 128) {
        // Gf[row] = fft(G[row])
        const int row = bid - 64;
        const float* g = G + row * NN;
        for (int n = tid; n < NN; n += NT) buf0[n] = make_float2(g[n], 0.0f);
        fft4096<0>(buf0, buf1, W, tid);
        for (int n = tid; n < NN; n += NT) g_Gf[row][n] = buf0[n];
    } else {
        // Xf[i,b] = ifft(conj(D) * x[i,b])
        const int ib = bid - 128;
        const float* xp = x + ib * NN;
        for (int n = tid; n < NN; n += NT) {
            float s, c; sincospif((float)n * (1.0f / 4096.0f), &s, &c);
            float v = xp[n];
            buf0[n] = make_float2(v * c, -v * s);
        }
        fft4096<1>(buf0, buf1, W, tid);
        const float inv = 1.0f / (float)NN;
        for (int n = tid; n < NN; n += NT)
            g_Xf[ib][n] = make_float2(buf0[n].x * inv, buf0[n].y * inv);
    }
}

__global__ void __launch_bounds__(NT) ldr_main_kernel(float* __restrict__ out)
{
    extern __shared__ float2 s_mem[];
    float2* buf0 = s_mem;
    float2* buf1 = s_mem + NN;
    float2* acc  = s_mem + 2 * NN;
    float2* W    = s_mem + 3 * NN;
    const int tid = threadIdx.x;
    fill_twiddles(W, tid);

    const int j = blockIdx.x >> 5;    // cout index
    const int b = blockIdx.x & 31;    // batch index

    for (int n = tid; n < NN; n += NT) acc[n] = make_float2(0.0f, 0.0f);

    for (int i = 0; i < CIN; ++i) {
        const float2* __restrict__ xf = g_Xf[i * BATCH + b];
#pragma unroll 1
        for (int s = 0; s < RANK; ++s) {
            const int row = (i * COUT + j) * RANK + s;
            const float2* __restrict__ hf = g_Hf[row];
            // u = Hf .* Xf   (each thread owns the same n-indices throughout;
            //  cross-thread ordering handled by fft4096's opening barrier)
            for (int n = tid; n < NN; n += NT) buf0[n] = cmul(hf[n], xf[n]);
            fft4096<0>(buf0, buf1, W, tid);
            // t = D .* fft(u)
            for (int n = tid; n < NN; n += NT) {
                float sn, cn; sincospif((float)n * (1.0f / 4096.0f), &sn, &cn);
                buf0[n] = cmul(buf0[n], make_float2(cn, sn));
            }
            fft4096<0>(buf0, buf1, W, tid);
            // Yf += Gf .* Tf
            const float2* __restrict__ gf = g_Gf[row];
            for (int n = tid; n < NN; n += NT) acc[n] = cadd(acc[n], cmul(gf[n], buf0[n]));
        }
    }

    // out[j,b,:] = Re(ifft(acc))
    for (int n = tid; n < NN; n += NT) buf0[n] = acc[n];
    fft4096<1>(buf0, buf1, W, tid);
    float* op = out + (j * BATCH + b) * NN;
    const float inv = 1.0f / (float)NN;
    for (int n = tid; n < NN; n += NT) op[n] = buf0[n].x * inv;
}

extern "C" void kernel_launch(void* const* d_in, const int* in_sizes, int n_in,
                              void* d_out, int out_size)
{
    const float* x = (const float*)d_in[0];   // (4, 32, 4096)
    const float* G = (const float*)d_in[1];   // (4, 4, 4, 4096)
    const float* H = (const float*)d_in[2];   // (4, 4, 4, 4096)
    float* out = (float*)d_out;               // (4, 32, 4096)

    cudaFuncSetAttribute(ldr_prep_kernel, cudaFuncAttributeMaxDynamicSharedMemorySize, PREP_SMEM);
    cudaFuncSetAttribute(ldr_main_kernel, cudaFuncAttributeMaxDynamicSharedMemorySize, MAIN_SMEM);

    ldr_prep_kernel<<<256, NT, PREP_SMEM>>>(x, G, H);
    ldr_main_kernel<<<128, NT, MAIN_SMEM>>>(out);
}

// round 2
// speedup vs baseline: 1.5182x; 1.5182x over previous
#include <cuda_runtime.h>

// LDR toeplitz-displacement layer via FFT:
//   Hf = fft(D*H); Gf = fft(G); Xf = ifft(conj(D)*x)
//   Yf[j,b] = sum_{i,s} Gf[i,j,s] * fft( D * fft( Hf[i,j,s] * Xf[i,b] ) )
//   out[j,b] = Re( ifft( Yf[j,b] ) )
// 4096-pt FFT = register-resident radix-8 Stockham (4 stages), SoA smem with
// +i/8 padding (conflict-free early-stage scatters), ping-pong buffers.
// Last stage (s=512, k1=0) stays in registers at indices n = tid + 512k, which
// is exactly the first-stage read pattern -> all pointwise ops fused in regs.

#define NN    4096
#define NT    512
#define CIN   4
#define COUT  4
#define RANK  4
#define BATCH 32

#define PIDX(i) ((i) + ((i) >> 3))
#define NPAD   4608          // 4096 + 4096/8
#define WSIZE  3584          // max twiddle exponent 7*511 = 3577

__device__ float2 g_Hf[CIN*COUT*RANK][NN];   // 2 MB
__device__ float2 g_Gf[CIN*COUT*RANK][NN];   // 2 MB
__device__ float2 g_Xf[CIN*BATCH][NN];       // 4 MB

__device__ __forceinline__ float2 cmul(float2 a, float2 b) {
    return make_float2(a.x*b.x - a.y*b.y, a.x*b.y + a.y*b.x);
}
__device__ __forceinline__ float2 cadd(float2 a, float2 b) { return make_float2(a.x+b.x, a.y+b.y); }
__device__ __forceinline__ float2 csub(float2 a, float2 b) { return make_float2(a.x-b.x, a.y-b.y); }

// radix-8 butterfly in registers: v_out[k] = sum_m v_in[m] * W8^{±km}
template<int INV>
__device__ __forceinline__ void bf8(float2 v[8]) {
    const float C = 0.70710678118654752440f;
    float2 e0,e1,e2,e3,o0,o1,o2,o3;
    {   // DFT4 of (v0,v2,v4,v6)
        float2 t0 = cadd(v[0], v[4]);
        float2 t1 = csub(v[0], v[4]);
        float2 t2 = cadd(v[2], v[6]);
        float2 d  = csub(v[2], v[6]);
        float2 t3 = INV ? make_float2(-d.y, d.x) : make_float2(d.y, -d.x);
        e0 = cadd(t0,t2); e1 = cadd(t1,t3); e2 = csub(t0,t2); e3 = csub(t1,t3);
    }
    {   // DFT4 of (v1,v3,v5,v7)
        float2 t0 = cadd(v[1], v[5]);
        float2 t1 = csub(v[1], v[5]);
        float2 t2 = cadd(v[3], v[7]);
        float2 d  = csub(v[3], v[7]);
        float2 t3 = INV ? make_float2(-d.y, d.x) : make_float2(d.y, -d.x);
        o0 = cadd(t0,t2); o1 = cadd(t1,t3); o2 = csub(t0,t2); o3 = csub(t1,t3);
    }
    float2 w1o, w2o, w3o;
    if (!INV) {
        w1o = make_float2(C*(o1.x + o1.y), C*(o1.y - o1.x));      // *(1-i)/sqrt2
        w2o = make_float2(o2.y, -o2.x);                            // *(-i)
        w3o = make_float2(C*(o3.y - o3.x), C*(-(o3.x + o3.y)));    // *(-1-i)/sqrt2
    } else {
        w1o = make_float2(C*(o1.x - o1.y), C*(o1.y + o1.x));       // *(1+i)/sqrt2
        w2o = make_float2(-o2.y, o2.x);                            // *(+i)
        w3o = make_float2(C*(-(o3.x + o3.y)), C*(o3.x - o3.y));    // *(-1+i)/sqrt2
    }
    v[0] = cadd(e0, o0);  v[4] = csub(e0, o0);
    v[1] = cadd(e1, w1o); v[5] = csub(e1, w1o);
    v[2] = cadd(e2, w2o); v[6] = csub(e2, w2o);
    v[3] = cadd(e3, w3o); v[7] = csub(e3, w3o);
}

// butterfly + twiddle + scatter to smem (Stockham stage with s = 1<<sshift)
template<int INV>
__device__ __forceinline__ void stage_store(float2 v[8], float* __restrict__ sre,
                                            float* __restrict__ sim,
                                            const float2* __restrict__ W,
                                            int u, int sshift) {
    bf8<INV>(v);
    const int s  = 1 << sshift;
    const int k1 = u & ~(s - 1);
    const int base = u + 7 * k1;
#pragma unroll
    for (int k = 0; k < 8; ++k) {
        float2 o = v[k];
        if (k) {
            float2 w = W[k * k1];
            if (INV) w.y = -w.y;
            o = cmul(o, w);
        }
        const int idx = PIDX(base + k * s);
        sre[idx] = o.x;
        sim[idx] = o.y;
    }
}

__device__ __forceinline__ void stage_load(float2 v[8], const float* __restrict__ sre,
                                           const float* __restrict__ sim, int tid) {
#pragma unroll
    for (int k = 0; k < 8; ++k) {
        const int idx = PIDX(tid + 512 * k);
        v[k] = make_float2(sre[idx], sim[idx]);
    }
}

// In: v[k] = x[tid + 512k]. Out: v[k] = X[tid + 512k] (no 1/N scale for INV).
template<int INV>
__device__ __forceinline__ void fft4096r8(float2 v[8],
                                          float* s0re, float* s0im,
                                          float* s1re, float* s1im,
                                          const float2* __restrict__ W, int tid) {
    __syncthreads();                               // prior consumers of s0 done
    stage_store<INV>(v, s0re, s0im, W, tid, 0);    // s = 1
    __syncthreads();
    stage_load(v, s0re, s0im, tid);
    stage_store<INV>(v, s1re, s1im, W, tid, 3);    // s = 8  (other buffer: no sync)
    __syncthreads();
    stage_load(v, s1re, s1im, tid);
    stage_store<INV>(v, s0re, s0im, W, tid, 6);    // s = 64
    __syncthreads();
    stage_load(v, s0re, s0im, tid);
    bf8<INV>(v);                                   // s = 512: k1 = 0, stays in regs
}

// ---- shared layouts (floats) ----
// prep: s0re[4608] s0im[4608] s1re[4608] s1im[4608] W[3584 float2]
#define PREP_SMEM ((4 * NPAD + 2 * WSIZE) * (int)sizeof(float))
// main: + D table[4096 float2]
#define MAIN_SMEM ((4 * NPAD + 2 * WSIZE + 2 * NN) * (int)sizeof(float))

__device__ __forceinline__ void fill_W(float2* W, int tid) {
    for (int k = tid; k < WSIZE; k += NT) {
        float s, c; sincospif((float)k * (1.0f / 2048.0f), &s, &c);
        W[k] = make_float2(c, -s);
    }
}

__global__ void __launch_bounds__(NT, 1) ldr_prep_kernel(const float* __restrict__ x,
                                                         const float* __restrict__ G,
                                                         const float* __restrict__ H)
{
    extern __shared__ float smemf[];
    float* s0re = smemf;
    float* s0im = smemf + NPAD;
    float* s1re = smemf + 2 * NPAD;
    float* s1im = smemf + 3 * NPAD;
    float2* W   = (float2*)(smemf + 4 * NPAD);
    const int tid = threadIdx.x;
    fill_W(W, tid);

    const int bid = blockIdx.x;
    float2 v[8];
    if (bid < 64) {                       // Hf = fft(D * H)
        const float* h = H + bid * NN;
#pragma unroll
        for (int k = 0; k < 8; ++k) {
            const int n = tid + 512 * k;
            float s, c; sincospif((float)n * (1.0f / 4096.0f), &s, &c);
            const float val = h[n];
            v[k] = make_float2(val * c, val * s);
        }
        fft4096r8<0>(v, s0re, s0im, s1re, s1im, W, tid);
#pragma unroll
        for (int k = 0; k < 8; ++k) g_Hf[bid][tid + 512 * k] = v[k];
    } else if (bid < 128) {               // Gf = fft(G)
        const float* g = G + (bid - 64) * NN;
#pragma unroll
        for (int k = 0; k < 8; ++k) v[k] = make_float2(g[tid + 512 * k], 0.0f);
        fft4096r8<0>(v, s0re, s0im, s1re, s1im, W, tid);
#pragma unroll
        for (int k = 0; k < 8; ++k) g_Gf[bid - 64][tid + 512 * k] = v[k];
    } else {                              // Xf = ifft(conj(D) * x) (with 1/N)
        const float* xp = x + (bid - 128) * NN;
#pragma unroll
        for (int k = 0; k < 8; ++k) {
            const int n = tid + 512 * k;
            float s, c; sincospif((float)n * (1.0f / 4096.0f), &s, &c);
            const float val = xp[n];
            v[k] = make_float2(val * c, -val * s);
        }
        fft4096r8<1>(v, s0re, s0im, s1re, s1im, W, tid);
        const float inv = 1.0f / (float)NN;
#pragma unroll
        for (int k = 0; k < 8; ++k)
            g_Xf[bid - 128][tid + 512 * k] = make_float2(v[k].x * inv, v[k].y * inv);
    }
}

__global__ void __launch_bounds__(NT, 1) ldr_main_kernel(float* __restrict__ out)
{
    extern __shared__ float smemf[];
    float* s0re = smemf;
    float* s0im = smemf + NPAD;
    float* s1re = smemf + 2 * NPAD;
    float* s1im = smemf + 3 * NPAD;
    float2* W   = (float2*)(smemf + 4 * NPAD);
    float2* Dt  = W + WSIZE;
    const int tid = threadIdx.x;
    fill_W(W, tid);
    // D[n] = exp(i*pi*n/N); each thread writes & later reads the same entries
    for (int n = tid; n < NN; n += NT) {
        float s, c; sincospif((float)n * (1.0f / 4096.0f), &s, &c);
        Dt[n] = make_float2(c, s);
    }

    const int j = blockIdx.x >> 5;
    const int b = blockIdx.x & 31;

    float2 acc[8];
#pragma unroll
    for (int k = 0; k < 8; ++k) acc[k] = make_float2(0.0f, 0.0f);

    float2 v[8];
    for (int i = 0; i < CIN; ++i) {
        const float2* __restrict__ xf = g_Xf[i * BATCH + b];
#pragma unroll 1
        for (int s = 0; s < RANK; ++s) {
            const int row = (i * COUT + j) * RANK + s;
            const float2* __restrict__ hf = g_Hf[row];
            const float2* __restrict__ gf = g_Gf[row];
            // u = Hf .* Xf (regs)
#pragma unroll
            for (int k = 0; k < 8; ++k) {
                const int n = tid + 512 * k;
                v[k] = cmul(hf[n], xf[n]);
            }
            fft4096r8<0>(v, s0re, s0im, s1re, s1im, W, tid);
            // t = D .* fft(u) (regs)
#pragma unroll
            for (int k = 0; k < 8; ++k) v[k] = cmul(v[k], Dt[tid + 512 * k]);
            fft4096r8<0>(v, s0re, s0im, s1re, s1im, W, tid);
            // Yf += Gf .* Tf (regs)
#pragma unroll
            for (int k = 0; k < 8; ++k)
                acc[k] = cadd(acc[k], cmul(gf[tid + 512 * k], v[k]));
        }
    }

    // out = Re(ifft(acc)) / N
    fft4096r8<1>(acc, s0re, s0im, s1re, s1im, W, tid);
    float* op = out + (j * BATCH + b) * NN;
    const float inv = 1.0f / (float)NN;
#pragma unroll
    for (int k = 0; k < 8; ++k) op[tid + 512 * k] = acc[k].x * inv;
}

extern "C" void kernel_launch(void* const* d_in, const int* in_sizes, int n_in,
                              void* d_out, int out_size)
{
    const float* x = (const float*)d_in[0];   // (4, 32, 4096)
    const float* G = (const float*)d_in[1];   // (4, 4, 4, 4096)
    const float* H = (const float*)d_in[2];   // (4, 4, 4, 4096)
    float* out = (float*)d_out;               // (4, 32, 4096)

    cudaFuncSetAttribute(ldr_prep_kernel, cudaFuncAttributeMaxDynamicSharedMemorySize, PREP_SMEM);
    cudaFuncSetAttribute(ldr_main_kernel, cudaFuncAttributeMaxDynamicSharedMemorySize, MAIN_SMEM);

    ldr_prep_kernel<<<256, NT, PREP_SMEM>>>(x, G, H);
    ldr_main_kernel<<<128, NT, MAIN_SMEM>>>(out);
}

// round 3
// speedup vs baseline: 1.6442x; 1.0830x over previous
#include <cuda_runtime.h>

// LDR toeplitz-displacement layer via FFT:
//   Hf = fft(D*H); Gf = fft(G); Xf = ifft(conj(D)*x)
//   Yf[j,b] = sum_{i,s} Gf[i,j,s] * fft( D * fft( Hf[i,j,s] * Xf[i,b] ) )
//   out[j,b] = Re( ifft( Yf[j,b] ) )
// 4096-pt FFT = register-resident radix-8 Stockham (4 stages, last in regs),
// SoA smem with +i/8 padding. Twiddles: 1 LDS per stage, powers in registers.
// Diagonal D factored as per-thread register * compile-time 16th roots.
// Buffer-parity alternation: 3 barriers per FFT.

#define NN    4096
#define NT    512
#define CIN   4
#define COUT  4
#define RANK  4
#define BATCH 32

#define PIDX(i) ((i) + ((i) >> 3))
#define NPAD   4608          // 4096 + 4096/8
#define WSIZE  512           // only W[k1], k1 <= 511

__device__ float2 g_Hf[CIN*COUT*RANK][NN];   // 2 MB
__device__ float2 g_Gf[CIN*COUT*RANK][NN];   // 2 MB
__device__ float2 g_Xf[CIN*BATCH][NN];       // 4 MB

__device__ __forceinline__ float2 cmul(float2 a, float2 b) {
    return make_float2(a.x*b.x - a.y*b.y, a.x*b.y + a.y*b.x);
}
__device__ __forceinline__ float2 cadd(float2 a, float2 b) { return make_float2(a.x+b.x, a.y+b.y); }
__device__ __forceinline__ float2 csub(float2 a, float2 b) { return make_float2(a.x-b.x, a.y-b.y); }

// radix-8 butterfly in registers
template<int INV>
__device__ __forceinline__ void bf8(float2 v[8]) {
    const float C = 0.70710678118654752440f;
    float2 e0,e1,e2,e3,o0,o1,o2,o3;
    {
        float2 t0 = cadd(v[0], v[4]);
        float2 t1 = csub(v[0], v[4]);
        float2 t2 = cadd(v[2], v[6]);
        float2 d  = csub(v[2], v[6]);
        float2 t3 = INV ? make_float2(-d.y, d.x) : make_float2(d.y, -d.x);
        e0 = cadd(t0,t2); e1 = cadd(t1,t3); e2 = csub(t0,t2); e3 = csub(t1,t3);
    }
    {
        float2 t0 = cadd(v[1], v[5]);
        float2 t1 = csub(v[1], v[5]);
        float2 t2 = cadd(v[3], v[7]);
        float2 d  = csub(v[3], v[7]);
        float2 t3 = INV ? make_float2(-d.y, d.x) : make_float2(d.y, -d.x);
        o0 = cadd(t0,t2); o1 = cadd(t1,t3); o2 = csub(t0,t2); o3 = csub(t1,t3);
    }
    float2 w1o, w2o, w3o;
    if (!INV) {
        w1o = make_float2(C*(o1.x + o1.y), C*(o1.y - o1.x));
        w2o = make_float2(o2.y, -o2.x);
        w3o = make_float2(C*(o3.y - o3.x), C*(-(o3.x + o3.y)));
    } else {
        w1o = make_float2(C*(o1.x - o1.y), C*(o1.y + o1.x));
        w2o = make_float2(-o2.y, o2.x);
        w3o = make_float2(C*(-(o3.x + o3.y)), C*(o3.x - o3.y));
    }
    v[0] = cadd(e0, o0);  v[4] = csub(e0, o0);
    v[1] = cadd(e1, w1o); v[5] = csub(e1, w1o);
    v[2] = cadd(e2, w2o); v[6] = csub(e2, w2o);
    v[3] = cadd(e3, w3o); v[7] = csub(e3, w3o);
}

// butterfly + twiddle(powers of W[k1]) + scatter to smem
template<int INV>
__device__ __forceinline__ void stage_store(float2 v[8], float* __restrict__ sre,
                                            float* __restrict__ sim,
                                            const float2* __restrict__ W,
                                            int u, int sshift) {
    bf8<INV>(v);
    const int s  = 1 << sshift;
    const int k1 = u & ~(s - 1);
    const int base = u + 7 * k1;
    float2 w1 = W[k1];
    if (INV) w1.y = -w1.y;
    const float2 w2 = cmul(w1, w1);
    const float2 w3 = cmul(w2, w1);
    const float2 w4 = cmul(w2, w2);
    const float2 w5 = cmul(w3, w2);
    const float2 w6 = cmul(w3, w3);
    const float2 w7 = cmul(w4, w3);
    float2 o;
    int idx;
    idx = PIDX(base);         o = v[0];          sre[idx] = o.x; sim[idx] = o.y;
    idx = PIDX(base + s);     o = cmul(v[1],w1); sre[idx] = o.x; sim[idx] = o.y;
    idx = PIDX(base + 2*s);   o = cmul(v[2],w2); sre[idx] = o.x; sim[idx] = o.y;
    idx = PIDX(base + 3*s);   o = cmul(v[3],w3); sre[idx] = o.x; sim[idx] = o.y;
    idx = PIDX(base + 4*s);   o = cmul(v[4],w4); sre[idx] = o.x; sim[idx] = o.y;
    idx = PIDX(base + 5*s);   o = cmul(v[5],w5); sre[idx] = o.x; sim[idx] = o.y;
    idx = PIDX(base + 6*s);   o = cmul(v[6],w6); sre[idx] = o.x; sim[idx] = o.y;
    idx = PIDX(base + 7*s);   o = cmul(v[7],w7); sre[idx] = o.x; sim[idx] = o.y;
}

__device__ __forceinline__ void stage_load(float2 v[8], const float* __restrict__ sre,
                                           const float* __restrict__ sim, int tid) {
#pragma unroll
    for (int k = 0; k < 8; ++k) {
        const int idx = PIDX(tid + 512 * k);
        v[k] = make_float2(sre[idx], sim[idx]);
    }
}

// In: v[k] = x[tid+512k]. Out: v[k] = X[tid+512k] (no 1/N scale for INV).
// PAR selects which ping-pong buffer is written first; consecutive calls must
// alternate PAR so the first (unsynced) store targets a buffer whose last
// readers are already behind a barrier.
template<int INV, int PAR>
__device__ __forceinline__ void fft4096r8(float2 v[8],
                                          float* s0re, float* s0im,
                                          float* s1re, float* s1im,
                                          const float2* __restrict__ W, int tid) {
    float* Are = PAR ? s1re : s0re;
    float* Aim = PAR ? s1im : s0im;
    float* Bre = PAR ? s0re : s1re;
    float* Bim = PAR ? s0im : s1im;
    stage_store<INV>(v, Are, Aim, W, tid, 0);    // s = 1
    __syncthreads();
    stage_load(v, Are, Aim, tid);
    stage_store<INV>(v, Bre, Bim, W, tid, 3);    // s = 8
    __syncthreads();
    stage_load(v, Bre, Bim, tid);
    stage_store<INV>(v, Are, Aim, W, tid, 6);    // s = 64
    __syncthreads();
    stage_load(v, Are, Aim, tid);
    bf8<INV>(v);                                 // s = 512: k1 = 0, in regs
}

// smem: s0re[4608] s0im[4608] s1re[4608] s1im[4608] W[512 float2]
#define LDR_SMEM ((4 * NPAD + 2 * WSIZE) * (int)sizeof(float))

__device__ __forceinline__ void fill_W(float2* W, int tid) {
    if (tid < WSIZE) {
        float s, c; sincospif((float)tid * (1.0f / 2048.0f), &s, &c);
        W[tid] = make_float2(c, -s);
    }
}

__global__ void __launch_bounds__(NT, 1) ldr_prep_kernel(const float* __restrict__ x,
                                                         const float* __restrict__ G,
                                                         const float* __restrict__ H)
{
    extern __shared__ float smemf[];
    float* s0re = smemf;
    float* s0im = smemf + NPAD;
    float* s1re = smemf + 2 * NPAD;
    float* s1im = smemf + 3 * NPAD;
    float2* W   = (float2*)(smemf + 4 * NPAD);
    const int tid = threadIdx.x;
    fill_W(W, tid);
    __syncthreads();

    const int bid = blockIdx.x;
    float2 v[8];
    if (bid < 64) {                       // Hf = fft(D * H)
        const float* h = H + bid * NN;
#pragma unroll
        for (int k = 0; k < 8; ++k) {
            const int n = tid + 512 * k;
            float s, c; sincospif((float)n * (1.0f / 4096.0f), &s, &c);
            const float val = h[n];
            v[k] = make_float2(val * c, val * s);
        }
        fft4096r8<0,0>(v, s0re, s0im, s1re, s1im, W, tid);
#pragma unroll
        for (int k = 0; k < 8; ++k) g_Hf[bid][tid + 512 * k] = v[k];
    } else if (bid < 128) {               // Gf = fft(G)
        const float* g = G + (bid - 64) * NN;
#pragma unroll
        for (int k = 0; k < 8; ++k) v[k] = make_float2(g[tid + 512 * k], 0.0f);
        fft4096r8<0,0>(v, s0re, s0im, s1re, s1im, W, tid);
#pragma unroll
        for (int k = 0; k < 8; ++k) g_Gf[bid - 64][tid + 512 * k] = v[k];
    } else {                              // Xf = ifft(conj(D) * x) (with 1/N)
        const float* xp = x + (bid - 128) * NN;
#pragma unroll
        for (int k = 0; k < 8; ++k) {
            const int n = tid + 512 * k;
            float s, c; sincospif((float)n * (1.0f / 4096.0f), &s, &c);
            const float val = xp[n];
            v[k] = make_float2(val * c, -val * s);
        }
        fft4096r8<1,0>(v, s0re, s0im, s1re, s1im, W, tid);
        const float inv = 1.0f / (float)NN;
#pragma unroll
        for (int k = 0; k < 8; ++k)
            g_Xf[bid - 128][tid + 512 * k] = make_float2(v[k].x * inv, v[k].y * inv);
    }
}

__global__ void __launch_bounds__(NT, 1) ldr_main_kernel(float* __restrict__ out)
{
    extern __shared__ float smemf[];
    float* s0re = smemf;
    float* s0im = smemf + NPAD;
    float* s1re = smemf + 2 * NPAD;
    float* s1im = smemf + 3 * NPAD;
    float2* W   = (float2*)(smemf + 4 * NPAD);
    const int tid = threadIdx.x;
    fill_W(W, tid);

    // D[tid + 512k] = exp(i*pi*tid/4096) * exp(i*pi*k/8): precompute 8 regs
    float2 dk[8];
    {
        float ss, cc; sincospif((float)tid * (1.0f / 4096.0f), &ss, &cc);
        const float2 d0 = make_float2(cc, ss);
        const float c8c[8] = {1.0f, 0.92387953251128675613f, 0.70710678118654752440f,
                              0.38268343236508977172f, 0.0f, -0.38268343236508977172f,
                              -0.70710678118654752440f, -0.92387953251128675613f};
        const float c8s[8] = {0.0f, 0.38268343236508977172f, 0.70710678118654752440f,
                              0.92387953251128675613f, 1.0f, 0.92387953251128675613f,
                              0.70710678118654752440f, 0.38268343236508977172f};
#pragma unroll
        for (int k = 0; k < 8; ++k) dk[k] = cmul(d0, make_float2(c8c[k], c8s[k]));
    }
    __syncthreads();   // W visible

    const int j = blockIdx.x >> 5;
    const int b = blockIdx.x & 31;

    float2 acc[8];
#pragma unroll
    for (int k = 0; k < 8; ++k) acc[k] = make_float2(0.0f, 0.0f);

    float2 v[8];
    for (int i = 0; i < CIN; ++i) {
        const float2* __restrict__ xf = g_Xf[i * BATCH + b];
#pragma unroll 1
        for (int s = 0; s < RANK; ++s) {
            const int row = (i * COUT + j) * RANK + s;
            const float2* __restrict__ hf = g_Hf[row];
            const float2* __restrict__ gf = g_Gf[row];
#pragma unroll
            for (int k = 0; k < 8; ++k) {
                const int n = tid + 512 * k;
                v[k] = cmul(hf[n], xf[n]);
            }
            fft4096r8<0,0>(v, s0re, s0im, s1re, s1im, W, tid);
#pragma unroll
            for (int k = 0; k < 8; ++k) v[k] = cmul(v[k], dk[k]);
            fft4096r8<0,1>(v, s0re, s0im, s1re, s1im, W, tid);
#pragma unroll
            for (int k = 0; k < 8; ++k)
                acc[k] = cadd(acc[k], cmul(gf[tid + 512 * k], v[k]));
        }
    }

    // out = Re(ifft(acc)) / N    (call #33: parity 0, alternation preserved)
    fft4096r8<1,0>(acc, s0re, s0im, s1re, s1im, W, tid);
    float* op = out + (j * BATCH + b) * NN;
    const float inv = 1.0f / (float)NN;
#pragma unroll
    for (int k = 0; k < 8; ++k) op[tid + 512 * k] = acc[k].x * inv;
}

extern "C" void kernel_launch(void* const* d_in, const int* in_sizes, int n_in,
                              void* d_out, int out_size)
{
    const float* x = (const float*)d_in[0];   // (4, 32, 4096)
    const float* G = (const float*)d_in[1];   // (4, 4, 4, 4096)
    const float* H = (const float*)d_in[2];   // (4, 4, 4, 4096)
    float* out = (float*)d_out;               // (4, 32, 4096)

    cudaFuncSetAttribute(ldr_prep_kernel, cudaFuncAttributeMaxDynamicSharedMemorySize, LDR_SMEM);
    cudaFuncSetAttribute(ldr_main_kernel, cudaFuncAttributeMaxDynamicSharedMemorySize, LDR_SMEM);

    ldr_prep_kernel<<<256, NT, LDR_SMEM>>>(x, G, H);
    ldr_main_kernel<<<128, NT, LDR_SMEM>>>(out);
}

// round 4
// speedup vs baseline: 2.5093x; 1.5261x over previous
#include <cuda_runtime.h>

// LDR toeplitz-displacement layer via FFT with 2-term real packing.
//   Hf = fft(D*H); Gf = fft(G); Xf = ifft(conj(D)*x)
//   Key identity: t = D * fft(Hf⊙Xf) is REAL (h,x real). So two terms pack as
//   z = u1 + i*u2; W = fft(D ⊙ fft(z)) = Tf1 + i*Tf2, with Tf Hermitian:
//   Tf1[k] = (W[k]+conj(W[-k]))/2, Tf2[k] = -i(W[k]-conj(W[-k]))/2.
//   acc += Gf1⊙Tf1 + Gf2⊙Tf2 ; final out = Re(ifft(acc)) / (2N) (½ folded).
// FFT: register radix-8 Stockham, 4 stages (last in regs), AoS float2 smem
// with +i/8 padding, twiddle powers from one LDS, strict buffer alternation.

#define NN    4096
#define NT    512
#define CIN   4
#define COUT  4
#define RANK  4
#define BATCH 32

#define PIDX(i) ((i) + ((i) >> 3))
#define NPAD   4608
#define WSIZE  512

__device__ float2 g_Hf[CIN*COUT*RANK][NN];   // 2 MB
__device__ float2 g_Gf[CIN*COUT*RANK][NN];   // 2 MB
__device__ float2 g_Xf[CIN*BATCH][NN];       // 4 MB

__device__ __forceinline__ float2 cmul(float2 a, float2 b) {
    return make_float2(a.x*b.x - a.y*b.y, a.x*b.y + a.y*b.x);
}
__device__ __forceinline__ float2 cadd(float2 a, float2 b) { return make_float2(a.x+b.x, a.y+b.y); }
__device__ __forceinline__ float2 csub(float2 a, float2 b) { return make_float2(a.x-b.x, a.y-b.y); }

template<int INV>
__device__ __forceinline__ void bf8(float2 v[8]) {
    const float C = 0.70710678118654752440f;
    float2 e0,e1,e2,e3,o0,o1,o2,o3;
    {
        float2 t0 = cadd(v[0], v[4]);
        float2 t1 = csub(v[0], v[4]);
        float2 t2 = cadd(v[2], v[6]);
        float2 d  = csub(v[2], v[6]);
        float2 t3 = INV ? make_float2(-d.y, d.x) : make_float2(d.y, -d.x);
        e0 = cadd(t0,t2); e1 = cadd(t1,t3); e2 = csub(t0,t2); e3 = csub(t1,t3);
    }
    {
        float2 t0 = cadd(v[1], v[5]);
        float2 t1 = csub(v[1], v[5]);
        float2 t2 = cadd(v[3], v[7]);
        float2 d  = csub(v[3], v[7]);
        float2 t3 = INV ? make_float2(-d.y, d.x) : make_float2(d.y, -d.x);
        o0 = cadd(t0,t2); o1 = cadd(t1,t3); o2 = csub(t0,t2); o3 = csub(t1,t3);
    }
    float2 w1o, w2o, w3o;
    if (!INV) {
        w1o = make_float2(C*(o1.x + o1.y), C*(o1.y - o1.x));
        w2o = make_float2(o2.y, -o2.x);
        w3o = make_float2(C*(o3.y - o3.x), C*(-(o3.x + o3.y)));
    } else {
        w1o = make_float2(C*(o1.x - o1.y), C*(o1.y + o1.x));
        w2o = make_float2(-o2.y, o2.x);
        w3o = make_float2(C*(-(o3.x + o3.y)), C*(o3.x - o3.y));
    }
    v[0] = cadd(e0, o0);  v[4] = csub(e0, o0);
    v[1] = cadd(e1, w1o); v[5] = csub(e1, w1o);
    v[2] = cadd(e2, w2o); v[6] = csub(e2, w2o);
    v[3] = cadd(e3, w3o); v[7] = csub(e3, w3o);
}

template<int INV>
__device__ __forceinline__ void stage_store(float2 v[8], float2* __restrict__ sb,
                                            const float2* __restrict__ W,
                                            int u, int sshift) {
    bf8<INV>(v);
    const int s  = 1 << sshift;
    const int k1 = u & ~(s - 1);
    const int base = u + 7 * k1;
    float2 w1 = W[k1];
    if (INV) w1.y = -w1.y;
    const float2 w2 = cmul(w1, w1);
    const float2 w3 = cmul(w2, w1);
    const float2 w4 = cmul(w2, w2);
    const float2 w5 = cmul(w3, w2);
    const float2 w6 = cmul(w3, w3);
    const float2 w7 = cmul(w4, w3);
    sb[PIDX(base)]         = v[0];
    sb[PIDX(base + s)]     = cmul(v[1], w1);
    sb[PIDX(base + 2*s)]   = cmul(v[2], w2);
    sb[PIDX(base + 3*s)]   = cmul(v[3], w3);
    sb[PIDX(base + 4*s)]   = cmul(v[4], w4);
    sb[PIDX(base + 5*s)]   = cmul(v[5], w5);
    sb[PIDX(base + 6*s)]   = cmul(v[6], w6);
    sb[PIDX(base + 7*s)]   = cmul(v[7], w7);
}

__device__ __forceinline__ void stage_load(float2 v[8], const float2* __restrict__ sb, int tid) {
#pragma unroll
    for (int k = 0; k < 8; ++k) v[k] = sb[PIDX(tid + 512 * k)];
}

// Stores go to buffers: PAR, PAR^1, PAR (strict global alternation across all
// exchanges in the block; one barrier between each store and its loads).
template<int INV, int PAR>
__device__ __forceinline__ void fft4096r8(float2 v[8], float2* b0, float2* b1,
                                          const float2* __restrict__ W, int tid) {
    float2* A = PAR ? b1 : b0;
    float2* B = PAR ? b0 : b1;
    stage_store<INV>(v, A, W, tid, 0);    // s = 1
    __syncthreads();
    stage_load(v, A, tid);
    stage_store<INV>(v, B, W, tid, 3);    // s = 8
    __syncthreads();
    stage_load(v, B, tid);
    stage_store<INV>(v, A, W, tid, 6);    // s = 64
    __syncthreads();
    stage_load(v, A, tid);
    bf8<INV>(v);                          // s = 512: k1 = 0, in regs
}

// smem: b0[4608] b1[4608] W[512]  (float2)
#define LDR_SMEM ((2 * NPAD + WSIZE) * (int)sizeof(float2))

__device__ __forceinline__ void fill_W(float2* W, int tid) {
    if (tid < WSIZE) {
        float s, c; sincospif((float)tid * (1.0f / 2048.0f), &s, &c);
        W[tid] = make_float2(c, -s);
    }
}

__global__ void __launch_bounds__(NT, 1) ldr_prep_kernel(const float* __restrict__ x,
                                                         const float* __restrict__ G,
                                                         const float* __restrict__ H)
{
    extern __shared__ float2 smem2[];
    float2* b0 = smem2;
    float2* b1 = smem2 + NPAD;
    float2* W  = smem2 + 2 * NPAD;
    const int tid = threadIdx.x;
    fill_W(W, tid);
    __syncthreads();

    const int bid = blockIdx.x;
    float2 v[8];
    if (bid < 64) {                       // Hf = fft(D * H)
        const float* h = H + bid * NN;
#pragma unroll
        for (int k = 0; k < 8; ++k) {
            const int n = tid + 512 * k;
            float s, c; sincospif((float)n * (1.0f / 4096.0f), &s, &c);
            const float val = h[n];
            v[k] = make_float2(val * c, val * s);
        }
        fft4096r8<0,0>(v, b0, b1, W, tid);
#pragma unroll
        for (int k = 0; k < 8; ++k) g_Hf[bid][tid + 512 * k] = v[k];
    } else if (bid < 128) {               // Gf = fft(G)
        const float* g = G + (bid - 64) * NN;
#pragma unroll
        for (int k = 0; k < 8; ++k) v[k] = make_float2(g[tid + 512 * k], 0.0f);
        fft4096r8<0,0>(v, b0, b1, W, tid);
#pragma unroll
        for (int k = 0; k < 8; ++k) g_Gf[bid - 64][tid + 512 * k] = v[k];
    } else {                              // Xf = ifft(conj(D) * x) (with 1/N)
        const float* xp = x + (bid - 128) * NN;
#pragma unroll
        for (int k = 0; k < 8; ++k) {
            const int n = tid + 512 * k;
            float s, c; sincospif((float)n * (1.0f / 4096.0f), &s, &c);
            const float val = xp[n];
            v[k] = make_float2(val * c, -val * s);
        }
        fft4096r8<1,0>(v, b0, b1, W, tid);
        const float inv = 1.0f / (float)NN;
#pragma unroll
        for (int k = 0; k < 8; ++k)
            g_Xf[bid - 128][tid + 512 * k] = make_float2(v[k].x * inv, v[k].y * inv);
    }
}

// one packed chain: two terms (rows r1, r2) sharing xf; accumulates into acc.
template<int PAR>
__device__ __forceinline__ void do_chain(const float2* __restrict__ hf1,
                                         const float2* __restrict__ hf2,
                                         const float2* __restrict__ gf1,
                                         const float2* __restrict__ gf2,
                                         const float2* __restrict__ xf,
                                         float2* b0, float2* b1,
                                         const float2* __restrict__ W,
                                         const float2 dk[8], float2 acc[8], int tid)
{
    float2 v[8];
#pragma unroll
    for (int k = 0; k < 8; ++k) {
        const int n = tid + 512 * k;
        const float2 xv = xf[n];
        const float2 u1 = cmul(hf1[n], xv);
        const float2 u2 = cmul(hf2[n], xv);
        v[k] = make_float2(u1.x - u2.y, u1.y + u2.x);   // u1 + i*u2
    }
    fft4096r8<0, PAR>(v, b0, b1, W, tid);
#pragma unroll
    for (int k = 0; k < 8; ++k) v[k] = cmul(v[k], dk[k]);
    fft4096r8<0, PAR ^ 1>(v, b0, b1, W, tid);

    // unpack exchange (store parity = PAR per strict alternation)
    float2* U = PAR ? b1 : b0;
#pragma unroll
    for (int k = 0; k < 8; ++k) U[PIDX(tid + 512 * k)] = v[k];
    __syncthreads();
#pragma unroll
    for (int k = 0; k < 8; ++k) {
        const int n   = tid + 512 * k;
        const int rev = (NN - n) & (NN - 1);
        const float2 ws = U[PIDX(rev)];
        // Tf1' = v + conj(ws); Tf2' = -i*(v - conj(ws))  (x2, folded into scale)
        const float2 t1 = make_float2(v[k].x + ws.x, v[k].y - ws.y);
        const float2 t2 = make_float2(v[k].y + ws.y, ws.x - v[k].x);
        acc[k] = cadd(acc[k], cadd(cmul(gf1[n], t1), cmul(gf2[n], t2)));
    }
}

__global__ void __launch_bounds__(NT, 1) ldr_main_kernel(float* __restrict__ out)
{
    extern __shared__ float2 smem2[];
    float2* b0 = smem2;
    float2* b1 = smem2 + NPAD;
    float2* W  = smem2 + 2 * NPAD;
    const int tid = threadIdx.x;
    fill_W(W, tid);

    // D[tid + 512k] = exp(i*pi*tid/4096) * exp(i*pi*k/8)
    float2 dk[8];
    {
        float ss, cc; sincospif((float)tid * (1.0f / 4096.0f), &ss, &cc);
        const float2 d0 = make_float2(cc, ss);
        const float c8c[8] = {1.0f, 0.92387953251128675613f, 0.70710678118654752440f,
                              0.38268343236508977172f, 0.0f, -0.38268343236508977172f,
                              -0.70710678118654752440f, -0.92387953251128675613f};
        const float c8s[8] = {0.0f, 0.38268343236508977172f, 0.70710678118654752440f,
                              0.92387953251128675613f, 1.0f, 0.92387953251128675613f,
                              0.70710678118654752440f, 0.38268343236508977172f};
#pragma unroll
        for (int k = 0; k < 8; ++k) dk[k] = cmul(d0, make_float2(c8c[k], c8s[k]));
    }
    __syncthreads();   // W visible

    const int j = blockIdx.x >> 5;
    const int b = blockIdx.x & 31;

    float2 acc[8];
#pragma unroll
    for (int k = 0; k < 8; ++k) acc[k] = make_float2(0.0f, 0.0f);

    // 8 packed chains: (i, spair) with rows (i*COUT+j)*RANK + {2sp, 2sp+1}
#pragma unroll 1
    for (int c = 0; c < 8; c += 2) {
        {
            const int i  = (c    ) >> 1, sp = (c    ) & 1;
            const int r1 = (i * COUT + j) * RANK + 2 * sp;
            do_chain<0>(g_Hf[r1], g_Hf[r1 + 1], g_Gf[r1], g_Gf[r1 + 1],
                        g_Xf[i * BATCH + b], b0, b1, W, dk, acc, tid);
        }
        {
            const int i  = (c + 1) >> 1, sp = (c + 1) & 1;
            const int r1 = (i * COUT + j) * RANK + 2 * sp;
            do_chain<1>(g_Hf[r1], g_Hf[r1 + 1], g_Gf[r1], g_Gf[r1 + 1],
                        g_Xf[i * BATCH + b], b0, b1, W, dk, acc, tid);
        }
    }

    // out = Re(ifft(acc)) / (2N)   (56 prior stores: parity 0 next)
    fft4096r8<1,0>(acc, b0, b1, W, tid);
    float* op = out + (j * BATCH + b) * NN;
    const float inv = 1.0f / (2.0f * (float)NN);
#pragma unroll
    for (int k = 0; k < 8; ++k) op[tid + 512 * k] = acc[k].x * inv;
}

extern "C" void kernel_launch(void* const* d_in, const int* in_sizes, int n_in,
                              void* d_out, int out_size)
{
    const float* x = (const float*)d_in[0];   // (4, 32, 4096)
    const float* G = (const float*)d_in[1];   // (4, 4, 4, 4096)
    const float* H = (const float*)d_in[2];   // (4, 4, 4, 4096)
    float* out = (float*)d_out;               // (4, 32, 4096)

    cudaFuncSetAttribute(ldr_prep_kernel, cudaFuncAttributeMaxDynamicSharedMemorySize, LDR_SMEM);
    cudaFuncSetAttribute(ldr_main_kernel, cudaFuncAttributeMaxDynamicSharedMemorySize, LDR_SMEM);

    ldr_prep_kernel<<<256, NT, LDR_SMEM>>>(x, G, H);
    ldr_main_kernel<<<128, NT, LDR_SMEM>>>(out);
}